// round 7
// baseline (speedup 1.0000x reference)
#include <cuda_runtime.h>
#include <math.h>

// ---------------------------------------------------------------------------
// PGA(3,0,1) blade algebra, computed at compile time.
// Blade order: 0:() 1:e0 2:e1 3:e2 4:e3 5:e01 6:e02 7:e03 8:e12 9:e13 10:e23
//              11:e012 12:e013 13:e023 14:e123 15:e0123
// ---------------------------------------------------------------------------

__host__ __device__ constexpr int pc4(int x) {
    return ((x >> 0) & 1) + ((x >> 1) & 1) + ((x >> 2) & 1) + ((x >> 3) & 1);
}

__host__ __device__ constexpr int I2M(int i) {
    return (i == 0) ? 0  : (i == 1) ? 1  : (i == 2) ? 2  : (i == 3) ? 4  :
           (i == 4) ? 8  : (i == 5) ? 3  : (i == 6) ? 5  : (i == 7) ? 9  :
           (i == 8) ? 6  : (i == 9) ? 10 : (i == 10) ? 12 : (i == 11) ? 7 :
           (i == 12) ? 11 : (i == 13) ? 13 : (i == 14) ? 14 : 15;
}

__host__ __device__ constexpr int M2I(int m) {
    return (m == 0) ? 0  : (m == 1) ? 1  : (m == 2) ? 2  : (m == 3) ? 5  :
           (m == 4) ? 3  : (m == 5) ? 6  : (m == 6) ? 8  : (m == 7) ? 11 :
           (m == 8) ? 4  : (m == 9) ? 7  : (m == 10) ? 9 : (m == 11) ? 12 :
           (m == 12) ? 10 : (m == 13) ? 13 : (m == 14) ? 14 : 15;
}

__host__ __device__ constexpr int msign(int a, int b) {
    int s = 0;
    if ((b >> 0) & 1) s += pc4(a >> 1);
    if ((b >> 1) & 1) s += pc4(a >> 2);
    if ((b >> 2) & 1) s += pc4(a >> 3);
    return (s & 1) ? -1 : 1;
}

__host__ __device__ constexpr int dsign(int m) { return msign(m, 15 ^ m); }

__host__ __device__ constexpr int jsign(int ma, int mb) {
    return dsign(ma) * dsign(mb) * msign(15 ^ ma, 15 ^ mb) * dsign(ma & mb);
}

// ---------------------------------------------------------------------------
// One thread per token; 256 threads / block; global I/O staged through a
// swizzled smem buffer (fully coalesced LDG/STG).
//
// Algebraic trim: the bilinear runs on RAW (un-normalized) x. Since
//   gp(xn_norm, xg(xn_norm)) = rinv^2 * gp(x, u(x))       (u = gated linear)
//   join term = x15_raw * rinv^3 * jn(x, u(x))
// all normalization folds into the 18 output-weight scalars. This removes
// the 16 normalize-MULs and the 16 residual-recovery MULs per token.
// ---------------------------------------------------------------------------
#define TPB 256

__device__ __forceinline__ int swz(int t, int c) {
    return 4 * t + (c ^ ((t >> 1) & 3));
}

__global__ void __launch_bounds__(TPB)
mvffn_kernel(const float* __restrict__ x,
             const float* __restrict__ w1, const float* __restrict__ v1, const float* __restrict__ b1,
             const float* __restrict__ wg, const float* __restrict__ vg, const float* __restrict__ bg,
             const float* __restrict__ wj, const float* __restrict__ vj, const float* __restrict__ bj,
             float* __restrict__ out, int ntok)
{
    __shared__ float4 stage[TPB * 4];

    const int tid  = threadIdx.x;
    const int base = blockIdx.x * TPB;
    const float4* xin4 = reinterpret_cast<const float4*>(x)  + (size_t)base * 4;
    float4*       out4 = reinterpret_cast<float4*>(out)      + (size_t)base * 4;
    const int     nf4  = min(TPB, ntok - base) * 4;

    // ---- coalesced load -> swizzled smem ----
    #pragma unroll
    for (int k = 0; k < 4; k++) {
        int f = tid + k * TPB;
        if (f < nf4) stage[swz(f >> 2, f & 3)] = xin4[f];
    }
    __syncthreads();

    const bool active = (base + tid < ntok);

    if (active) {
        float4 q0 = stage[swz(tid, 0)], q1 = stage[swz(tid, 1)];
        float4 q2 = stage[swz(tid, 2)], q3 = stage[swz(tid, 3)];

        // RAW x — kept unmodified; also serves as the residual.
        float xn[16] = { q0.x, q0.y, q0.z, q0.w,
                         q1.x, q1.y, q1.z, q1.w,
                         q2.x, q2.y, q2.z, q2.w,
                         q3.x, q3.y, q3.z, q3.w };

        // ---- norm factors over non-e0 blades: idx 0,2,3,4,8,9,10,14 ----
        float s = 1e-5f;
        s = fmaf(xn[0],  xn[0],  s);
        s = fmaf(xn[2],  xn[2],  s);
        s = fmaf(xn[3],  xn[3],  s);
        s = fmaf(xn[4],  xn[4],  s);
        s = fmaf(xn[8],  xn[8],  s);
        s = fmaf(xn[9],  xn[9],  s);
        s = fmaf(xn[10], xn[10], s);
        s = fmaf(xn[14], xn[14], s);
        const float rinv  = rsqrtf(s);
        const float rinv2 = rinv * rinv;
        const float rinv3 = rinv2 * rinv;
        const float nrm   = s * rinv;          // sqrt(s)

        // ---- gate: xp0 = w1[0]*xn_norm[0] + b1; G = gelu(xp0) ----
        const float4 w1a = *reinterpret_cast<const float4*>(w1);
        const float  w1e = w1[4];
        const float4 v1a = *reinterpret_cast<const float4*>(v1);

        const float xp0 = fmaf(w1a.x, xn[0] * rinv, b1[0]);
        const float G   = xp0 * normcdff(xp0);  // exact GELU

        // gate folded into first-linear weights; u_j = G*(W1 x_j + V1 x_j')
        const float W1f[5] = { G * w1a.x, G * w1a.y, G * w1a.z, G * w1a.w, G * w1e };
        const float V1f[4] = { G * v1a.x, G * v1a.y, G * v1a.z, G * v1a.w };
        // j=0 column carries the bias -> not homogeneous in x; restore
        // rinv^2 homogeneity by multiplying by nrm (= 1/rinv):
        const float u0 = (G * xp0) * nrm;

        // ---- bilinear on RAW x: gp_use, jn_use (scale folded out) ----
        float gp[16], jn[16];
        #pragma unroll
        for (int k = 0; k < 16; k++) { gp[k] = 0.f; jn[k] = 0.f; }

        #pragma unroll
        for (int j = 0; j < 16; j++) {
            const int mb = I2M(j);
            const int gB = pc4(mb);

            float uj;
            if (j == 0) {
                uj = u0;
            } else {
                uj = W1f[gB] * xn[j];
                if ((mb & 1) && gB < 4) uj = fmaf(V1f[gB], xn[M2I(mb ^ 1)], uj);
            }

            #pragma unroll
            for (int i = 0; i < 16; i++) {
                const int ma = I2M(i);
                if (!(ma & mb & 1)) {                  // e0^2 = 0
                    const int k = M2I(ma ^ mb);
                    if (msign(ma, mb) > 0) gp[k] = fmaf(xn[i],  uj, gp[k]);
                    else                   gp[k] = fmaf(xn[i], -uj, gp[k]);
                }
                if ((ma | mb) == 15) {                 // join support
                    const int k = M2I(ma & mb);
                    if (jsign(ma, mb) > 0) jn[k] = fmaf(xn[i],  uj, jn[k]);
                    else                   jn[k] = fmaf(xn[i], -uj, jn[k]);
                }
            }
        }

        // ---- output linears with all scales folded into the weights ----
        const float4 wga = *reinterpret_cast<const float4*>(wg);
        const float  wge = wg[4];
        const float4 vga = *reinterpret_cast<const float4*>(vg);
        const float4 wja = *reinterpret_cast<const float4*>(wj);
        const float  wje = wj[4];
        const float4 vja = *reinterpret_cast<const float4*>(vj);

        const float gfac = rinv2;                 // gp path scale
        const float jfac = xn[15] * rinv3;        // join path: x15_norm*rinv^2

        const float WG[5] = { wga.x * gfac, wga.y * gfac, wga.z * gfac,
                              wga.w * gfac, wge * gfac };
        const float VG[4] = { vga.x * gfac, vga.y * gfac, vga.z * gfac,
                              vga.w * gfac };
        const float WJ[5] = { wja.x * jfac, wja.y * jfac, wja.z * jfac,
                              wja.w * jfac, wje * jfac };
        const float VJ[4] = { vja.x * jfac, vja.y * jfac, vja.z * jfac,
                              vja.w * jfac };

        float o[16];
        #pragma unroll
        for (int d = 0; d < 16; d++) {
            const int m = I2M(d);
            const int g = pc4(m);
            float v = fmaf(WG[g], gp[d], xn[d]);   // residual = raw x[d]
            v = fmaf(WJ[g], jn[d], v);
            if ((m & 1) && g < 4) {
                const int sidx = M2I(m ^ 1);
                v = fmaf(VG[g], gp[sidx], v);
                v = fmaf(VJ[g], jn[sidx], v);
            }
            o[d] = v;
        }
        o[0] += bg[0] + bj[0];

        stage[swz(tid, 0)] = make_float4(o[0],  o[1],  o[2],  o[3]);
        stage[swz(tid, 1)] = make_float4(o[4],  o[5],  o[6],  o[7]);
        stage[swz(tid, 2)] = make_float4(o[8],  o[9],  o[10], o[11]);
        stage[swz(tid, 3)] = make_float4(o[12], o[13], o[14], o[15]);
    }
    __syncthreads();

    // ---- coalesced store from swizzled smem ----
    #pragma unroll
    for (int k = 0; k < 4; k++) {
        int f = tid + k * TPB;
        if (f < nf4) out4[f] = stage[swz(f >> 2, f & 3)];
    }
}

extern "C" void kernel_launch(void* const* d_in, const int* in_sizes, int n_in,
                              void* d_out, int out_size)
{
    const float* x  = (const float*)d_in[0];
    const float* w1 = (const float*)d_in[1];
    const float* v1 = (const float*)d_in[2];
    const float* b1 = (const float*)d_in[3];
    const float* wg = (const float*)d_in[4];
    const float* vg = (const float*)d_in[5];
    const float* bg = (const float*)d_in[6];
    const float* wj = (const float*)d_in[7];
    const float* vj = (const float*)d_in[8];
    const float* bj = (const float*)d_in[9];

    const int ntok   = in_sizes[0] / 16;
    const int blocks = (ntok + TPB - 1) / TPB;

    mvffn_kernel<<<blocks, TPB>>>(x, w1, v1, b1, wg, vg, bg, wj, vj, bj,
                                  (float*)d_out, ntok);
}

// round 8
// speedup vs baseline: 1.0025x; 1.0025x over previous
#include <cuda_runtime.h>
#include <math.h>

// ---------------------------------------------------------------------------
// PGA(3,0,1) blade algebra, computed at compile time.
// Blade order: 0:() 1:e0 2:e1 3:e2 4:e3 5:e01 6:e02 7:e03 8:e12 9:e13 10:e23
//              11:e012 12:e013 13:e023 14:e123 15:e0123
// ---------------------------------------------------------------------------

__host__ __device__ constexpr int pc4(int x) {
    return ((x >> 0) & 1) + ((x >> 1) & 1) + ((x >> 2) & 1) + ((x >> 3) & 1);
}

__host__ __device__ constexpr int I2M(int i) {
    return (i == 0) ? 0  : (i == 1) ? 1  : (i == 2) ? 2  : (i == 3) ? 4  :
           (i == 4) ? 8  : (i == 5) ? 3  : (i == 6) ? 5  : (i == 7) ? 9  :
           (i == 8) ? 6  : (i == 9) ? 10 : (i == 10) ? 12 : (i == 11) ? 7 :
           (i == 12) ? 11 : (i == 13) ? 13 : (i == 14) ? 14 : 15;
}

__host__ __device__ constexpr int M2I(int m) {
    return (m == 0) ? 0  : (m == 1) ? 1  : (m == 2) ? 2  : (m == 3) ? 5  :
           (m == 4) ? 3  : (m == 5) ? 6  : (m == 6) ? 8  : (m == 7) ? 11 :
           (m == 8) ? 4  : (m == 9) ? 7  : (m == 10) ? 9 : (m == 11) ? 12 :
           (m == 12) ? 10 : (m == 13) ? 13 : (m == 14) ? 14 : 15;
}

__host__ __device__ constexpr int msign(int a, int b) {
    int s = 0;
    if ((b >> 0) & 1) s += pc4(a >> 1);
    if ((b >> 1) & 1) s += pc4(a >> 2);
    if ((b >> 2) & 1) s += pc4(a >> 3);
    return (s & 1) ? -1 : 1;
}

__host__ __device__ constexpr int dsign(int m) { return msign(m, 15 ^ m); }

__host__ __device__ constexpr int jsign(int ma, int mb) {
    return dsign(ma) * dsign(mb) * msign(15 ^ ma, 15 ^ mb) * dsign(ma & mb);
}

// ---------------------------------------------------------------------------
// Two warps per 32 tokens: warp with (wid&1)==H computes output blades
// d in [8H, 8H+8). Each e0-blade's V-path source lives in the same half.
// ---------------------------------------------------------------------------

template<int H>
__device__ __forceinline__ void compute_half(
    const float xn[16],
    const float W1f[5], const float V1f[4], float u0,
    const float WG[5], const float VG[4],
    const float WJ[5], const float VJ[4],
    float biases, float o[8])
{
    float gp[8], jn[8];
    #pragma unroll
    for (int k = 0; k < 8; k++) { gp[k] = 0.f; jn[k] = 0.f; }

    #pragma unroll
    for (int j = 0; j < 16; j++) {
        const int mb = I2M(j);
        const int gB = pc4(mb);

        float uj;
        if (j == 0) {
            uj = u0;
        } else {
            uj = W1f[gB] * xn[j];
            if ((mb & 1) && gB < 4) uj = fmaf(V1f[gB], xn[M2I(mb ^ 1)], uj);
        }

        #pragma unroll
        for (int i = 0; i < 16; i++) {
            const int ma = I2M(i);
            if (!(ma & mb & 1)) {                   // e0^2 = 0
                const int k = M2I(ma ^ mb);
                if (k >= 8 * H && k < 8 * H + 8) {
                    if (msign(ma, mb) > 0) gp[k - 8 * H] = fmaf(xn[i],  uj, gp[k - 8 * H]);
                    else                   gp[k - 8 * H] = fmaf(xn[i], -uj, gp[k - 8 * H]);
                }
            }
            if ((ma | mb) == 15) {                  // join support
                const int k = M2I(ma & mb);
                if (k >= 8 * H && k < 8 * H + 8) {
                    if (jsign(ma, mb) > 0) jn[k - 8 * H] = fmaf(xn[i],  uj, jn[k - 8 * H]);
                    else                   jn[k - 8 * H] = fmaf(xn[i], -uj, jn[k - 8 * H]);
                }
            }
        }
    }

    #pragma unroll
    for (int dd = 0; dd < 8; dd++) {
        const int d = 8 * H + dd;
        const int m = I2M(d);
        const int g = pc4(m);
        float v = fmaf(WG[g], gp[dd], xn[d]);       // residual = raw x[d]
        v = fmaf(WJ[g], jn[dd], v);
        if ((m & 1) && g < 4) {
            const int sidx = M2I(m ^ 1) - 8 * H;    // same half by construction
            v = fmaf(VG[g], gp[sidx], v);
            v = fmaf(VJ[g], jn[sidx], v);
        }
        if (H == 0 && dd == 0) v += biases;
        o[dd] = v;
    }
}

// ---------------------------------------------------------------------------
// 256 threads / block, 128 tokens / block. Token tloc = (wid>>1)*32 + lane,
// half = wid & 1 (warp-uniform: no divergence). Coalesced global I/O via
// swizzled smem staging: smem4[4t + (c ^ ((t>>1)&3))] (conflict-free in both
// the coalesced phase and the per-token phase).
// ---------------------------------------------------------------------------
#define TPB      256
#define TOKS_BLK 128

__device__ __forceinline__ int swz(int t, int c) {
    return 4 * t + (c ^ ((t >> 1) & 3));
}

__global__ void __launch_bounds__(TPB)
mvffn_kernel(const float* __restrict__ x,
             const float* __restrict__ w1, const float* __restrict__ v1, const float* __restrict__ b1,
             const float* __restrict__ wg, const float* __restrict__ vg, const float* __restrict__ bg,
             const float* __restrict__ wj, const float* __restrict__ vj, const float* __restrict__ bj,
             float* __restrict__ out, int ntok)
{
    __shared__ float4 stage[TOKS_BLK * 4];

    const int tid  = threadIdx.x;
    const int base = blockIdx.x * TOKS_BLK;
    const float4* xin4 = reinterpret_cast<const float4*>(x)  + (size_t)base * 4;
    float4*       out4 = reinterpret_cast<float4*>(out)      + (size_t)base * 4;
    const int     nf4  = min(TOKS_BLK, ntok - base) * 4;      // float4s this block

    // ---- coalesced load -> swizzled smem (512 float4 = 2 iters) ----
    #pragma unroll
    for (int k = 0; k < 2; k++) {
        int f = tid + k * TPB;
        if (f < nf4) stage[swz(f >> 2, f & 3)] = xin4[f];
    }
    __syncthreads();

    const int wid  = tid >> 5;
    const int lane = tid & 31;
    const int tloc = (wid >> 1) * 32 + lane;    // 0..127
    const int half = wid & 1;                   // warp-uniform
    const bool active = (base + tloc < ntok);

    if (active) {
        float4 q0 = stage[swz(tloc, 0)], q1 = stage[swz(tloc, 1)];
        float4 q2 = stage[swz(tloc, 2)], q3 = stage[swz(tloc, 3)];

        // RAW x — also the residual. Normalization folded into output scales.
        float xn[16] = { q0.x, q0.y, q0.z, q0.w,
                         q1.x, q1.y, q1.z, q1.w,
                         q2.x, q2.y, q2.z, q2.w,
                         q3.x, q3.y, q3.z, q3.w };

        // ---- norm factors over non-e0 blades: idx 0,2,3,4,8,9,10,14 ----
        float s = 1e-5f;
        s = fmaf(xn[0],  xn[0],  s);
        s = fmaf(xn[2],  xn[2],  s);
        s = fmaf(xn[3],  xn[3],  s);
        s = fmaf(xn[4],  xn[4],  s);
        s = fmaf(xn[8],  xn[8],  s);
        s = fmaf(xn[9],  xn[9],  s);
        s = fmaf(xn[10], xn[10], s);
        s = fmaf(xn[14], xn[14], s);
        const float rinv  = rsqrtf(s);
        const float rinv2 = rinv * rinv;
        const float rinv3 = rinv2 * rinv;
        const float nrm   = s * rinv;            // sqrt(s)

        // ---- gate ----
        const float4 w1a = *reinterpret_cast<const float4*>(w1);
        const float  w1e = w1[4];
        const float4 v1a = *reinterpret_cast<const float4*>(v1);

        const float xp0 = fmaf(w1a.x, xn[0] * rinv, b1[0]);
        const float G   = xp0 * normcdff(xp0);   // exact GELU

        const float W1f[5] = { G * w1a.x, G * w1a.y, G * w1a.z, G * w1a.w, G * w1e };
        const float V1f[4] = { G * v1a.x, G * v1a.y, G * v1a.z, G * v1a.w };
        const float u0 = (G * xp0) * nrm;        // homogenize the bias column

        // ---- output weights with normalization folded in ----
        const float4 wga = *reinterpret_cast<const float4*>(wg);
        const float  wge = wg[4];
        const float4 vga = *reinterpret_cast<const float4*>(vg);
        const float4 wja = *reinterpret_cast<const float4*>(wj);
        const float  wje = wj[4];
        const float4 vja = *reinterpret_cast<const float4*>(vj);

        const float gfac = rinv2;                // gp path scale
        const float jfac = xn[15] * rinv3;       // join path scale

        const float WG[5] = { wga.x * gfac, wga.y * gfac, wga.z * gfac,
                              wga.w * gfac, wge * gfac };
        const float VG[4] = { vga.x * gfac, vga.y * gfac, vga.z * gfac,
                              vga.w * gfac };
        const float WJ[5] = { wja.x * jfac, wja.y * jfac, wja.z * jfac,
                              wja.w * jfac, wje * jfac };
        const float VJ[4] = { vja.x * jfac, vja.y * jfac, vja.z * jfac,
                              vja.w * jfac };

        const float biases = bg[0] + bj[0];

        float o[8];
        if (half == 0)
            compute_half<0>(xn, W1f, V1f, u0, WG, VG, WJ, VJ, biases, o);
        else
            compute_half<1>(xn, W1f, V1f, u0, WG, VG, WJ, VJ, biases, o);

        // write this half's 8 outputs (chunks 2*half, 2*half+1)
        stage[swz(tloc, 2 * half)]     = make_float4(o[0], o[1], o[2], o[3]);
        stage[swz(tloc, 2 * half + 1)] = make_float4(o[4], o[5], o[6], o[7]);
    }
    __syncthreads();

    // ---- coalesced store from swizzled smem ----
    #pragma unroll
    for (int k = 0; k < 2; k++) {
        int f = tid + k * TPB;
        if (f < nf4) out4[f] = stage[swz(f >> 2, f & 3)];
    }
}

extern "C" void kernel_launch(void* const* d_in, const int* in_sizes, int n_in,
                              void* d_out, int out_size)
{
    const float* x  = (const float*)d_in[0];
    const float* w1 = (const float*)d_in[1];
    const float* v1 = (const float*)d_in[2];
    const float* b1 = (const float*)d_in[3];
    const float* wg = (const float*)d_in[4];
    const float* vg = (const float*)d_in[5];
    const float* bg = (const float*)d_in[6];
    const float* wj = (const float*)d_in[7];
    const float* vj = (const float*)d_in[8];
    const float* bj = (const float*)d_in[9];

    const int ntok   = in_sizes[0] / 16;
    const int blocks = (ntok + TOKS_BLK - 1) / TOKS_BLK;

    mvffn_kernel<<<blocks, TPB>>>(x, w1, v1, b1, wg, vg, bg, wj, vj, bj,
                                  (float*)d_out, ntok);
}

// round 9
// speedup vs baseline: 1.0226x; 1.0201x over previous
#include <cuda_runtime.h>
#include <math.h>

// ---------------------------------------------------------------------------
// PGA(3,0,1) blade algebra, computed at compile time.
// Blade order: 0:() 1:e0 2:e1 3:e2 4:e3 5:e01 6:e02 7:e03 8:e12 9:e13 10:e23
//              11:e012 12:e013 13:e023 14:e123 15:e0123
// ---------------------------------------------------------------------------

__host__ __device__ constexpr int pc4(int x) {
    return ((x >> 0) & 1) + ((x >> 1) & 1) + ((x >> 2) & 1) + ((x >> 3) & 1);
}

__host__ __device__ constexpr int I2M(int i) {
    return (i == 0) ? 0  : (i == 1) ? 1  : (i == 2) ? 2  : (i == 3) ? 4  :
           (i == 4) ? 8  : (i == 5) ? 3  : (i == 6) ? 5  : (i == 7) ? 9  :
           (i == 8) ? 6  : (i == 9) ? 10 : (i == 10) ? 12 : (i == 11) ? 7 :
           (i == 12) ? 11 : (i == 13) ? 13 : (i == 14) ? 14 : 15;
}

__host__ __device__ constexpr int M2I(int m) {
    return (m == 0) ? 0  : (m == 1) ? 1  : (m == 2) ? 2  : (m == 3) ? 5  :
           (m == 4) ? 3  : (m == 5) ? 6  : (m == 6) ? 8  : (m == 7) ? 11 :
           (m == 8) ? 4  : (m == 9) ? 7  : (m == 10) ? 9 : (m == 11) ? 12 :
           (m == 12) ? 10 : (m == 13) ? 13 : (m == 14) ? 14 : 15;
}

__host__ __device__ constexpr int msign(int a, int b) {
    int s = 0;
    if ((b >> 0) & 1) s += pc4(a >> 1);
    if ((b >> 1) & 1) s += pc4(a >> 2);
    if ((b >> 2) & 1) s += pc4(a >> 3);
    return (s & 1) ? -1 : 1;
}

__host__ __device__ constexpr int dsign(int m) { return msign(m, 15 ^ m); }

__host__ __device__ constexpr int jsign(int ma, int mb) {
    return dsign(ma) * dsign(mb) * msign(15 ^ ma, 15 ^ mb) * dsign(ma & mb);
}

// ---------------------------------------------------------------------------
// Compile-time unroll driver: every iteration index is a constexpr, so all
// array subscripts below are literal constants -> guaranteed register
// promotion of xn/gp/jn (no local-memory spills possible by construction).
// ---------------------------------------------------------------------------
template<int I> struct IC { static constexpr int v = I; };

template<int N> struct Unroll {
    template<typename F>
    __device__ __forceinline__ static void run(F&& f) {
        Unroll<N - 1>::run(f);
        f(IC<N - 1>{});
    }
};
template<> struct Unroll<0> {
    template<typename F>
    __device__ __forceinline__ static void run(F&&) {}
};

// ---------------------------------------------------------------------------
// One thread per token; 256 threads / block; coalesced global I/O staged
// through a swizzled smem buffer. Bilinear runs on RAW x with normalization
// folded into output-weight scalars (R7 formulation, verified).
// ---------------------------------------------------------------------------
#define TPB 256

__device__ __forceinline__ int swz(int t, int c) {
    return 4 * t + (c ^ ((t >> 1) & 3));
}

__global__ void __launch_bounds__(TPB)
mvffn_kernel(const float* __restrict__ x,
             const float* __restrict__ w1, const float* __restrict__ v1, const float* __restrict__ b1,
             const float* __restrict__ wg, const float* __restrict__ vg, const float* __restrict__ bg,
             const float* __restrict__ wj, const float* __restrict__ vj, const float* __restrict__ bj,
             float* __restrict__ out, int ntok)
{
    __shared__ float4 stage[TPB * 4];

    const int tid  = threadIdx.x;
    const int base = blockIdx.x * TPB;
    const float4* xin4 = reinterpret_cast<const float4*>(x)  + (size_t)base * 4;
    float4*       out4 = reinterpret_cast<float4*>(out)      + (size_t)base * 4;
    const int     nf4  = min(TPB, ntok - base) * 4;

    // ---- coalesced load -> swizzled smem ----
    #pragma unroll
    for (int k = 0; k < 4; k++) {
        int f = tid + k * TPB;
        if (f < nf4) stage[swz(f >> 2, f & 3)] = xin4[f];
    }
    __syncthreads();

    if (base + tid < ntok) {
        float4 q0 = stage[swz(tid, 0)], q1 = stage[swz(tid, 1)];
        float4 q2 = stage[swz(tid, 2)], q3 = stage[swz(tid, 3)];

        // RAW x — also the residual.
        float xn[16] = { q0.x, q0.y, q0.z, q0.w,
                         q1.x, q1.y, q1.z, q1.w,
                         q2.x, q2.y, q2.z, q2.w,
                         q3.x, q3.y, q3.z, q3.w };

        // ---- norm factors over non-e0 blades: idx 0,2,3,4,8,9,10,14 ----
        float s = 1e-5f;
        s = fmaf(xn[0],  xn[0],  s);
        s = fmaf(xn[2],  xn[2],  s);
        s = fmaf(xn[3],  xn[3],  s);
        s = fmaf(xn[4],  xn[4],  s);
        s = fmaf(xn[8],  xn[8],  s);
        s = fmaf(xn[9],  xn[9],  s);
        s = fmaf(xn[10], xn[10], s);
        s = fmaf(xn[14], xn[14], s);
        const float rinv  = rsqrtf(s);
        const float rinv2 = rinv * rinv;
        const float rinv3 = rinv2 * rinv;
        const float nrm   = s * rinv;            // sqrt(s)

        // ---- gate: xp0 = w1[0]*xn_norm[0] + b1; G = exact GELU ----
        const float4 w1a = *reinterpret_cast<const float4*>(w1);
        const float  w1e = w1[4];
        const float4 v1a = *reinterpret_cast<const float4*>(v1);

        const float xp0 = fmaf(w1a.x, xn[0] * rinv, b1[0]);
        const float G   = xp0 * normcdff(xp0);

        const float W1f[5] = { G * w1a.x, G * w1a.y, G * w1a.z, G * w1a.w, G * w1e };
        const float V1f[4] = { G * v1a.x, G * v1a.y, G * v1a.z, G * v1a.w };
        const float u0 = (G * xp0) * nrm;        // homogenize the bias column

        // ---- bilinear on RAW x, all indices constexpr ----
        float gp[16], jn[16];
        Unroll<16>::run([&](auto K) {
            constexpr int k = decltype(K)::v;
            gp[k] = 0.f; jn[k] = 0.f;
        });

        Unroll<16>::run([&](auto J) {
            constexpr int j  = decltype(J)::v;
            constexpr int mb = I2M(j);
            constexpr int gB = pc4(mb);

            float uj;
            if constexpr (j == 0) {
                uj = u0;
            } else {
                uj = W1f[gB] * xn[j];
                if constexpr ((mb & 1) && gB < 4)
                    uj = fmaf(V1f[gB], xn[M2I(mb ^ 1)], uj);
            }

            Unroll<16>::run([&](auto I_) {
                constexpr int i  = decltype(I_)::v;
                constexpr int ma = I2M(i);
                if constexpr (!(ma & mb & 1)) {            // e0^2 = 0
                    constexpr int k = M2I(ma ^ mb);
                    if constexpr (msign(ma, mb) > 0) gp[k] = fmaf(xn[i],  uj, gp[k]);
                    else                             gp[k] = fmaf(xn[i], -uj, gp[k]);
                }
                if constexpr ((ma | mb) == 15) {           // join support
                    constexpr int k = M2I(ma & mb);
                    if constexpr (jsign(ma, mb) > 0) jn[k] = fmaf(xn[i],  uj, jn[k]);
                    else                             jn[k] = fmaf(xn[i], -uj, jn[k]);
                }
            });
        });

        // ---- output linears with normalization folded into the weights ----
        const float4 wga = *reinterpret_cast<const float4*>(wg);
        const float  wge = wg[4];
        const float4 vga = *reinterpret_cast<const float4*>(vg);
        const float4 wja = *reinterpret_cast<const float4*>(wj);
        const float  wje = wj[4];
        const float4 vja = *reinterpret_cast<const float4*>(vj);

        const float gfac = rinv2;                 // gp path scale
        const float jfac = xn[15] * rinv3;        // join path scale

        const float WG[5] = { wga.x * gfac, wga.y * gfac, wga.z * gfac,
                              wga.w * gfac, wge * gfac };
        const float VG[4] = { vga.x * gfac, vga.y * gfac, vga.z * gfac,
                              vga.w * gfac };
        const float WJ[5] = { wja.x * jfac, wja.y * jfac, wja.z * jfac,
                              wja.w * jfac, wje * jfac };
        const float VJ[4] = { vja.x * jfac, vja.y * jfac, vja.z * jfac,
                              vja.w * jfac };

        float o[16];
        Unroll<16>::run([&](auto D) {
            constexpr int d = decltype(D)::v;
            constexpr int m = I2M(d);
            constexpr int g = pc4(m);
            float v = fmaf(WG[g], gp[d], xn[d]);   // residual = raw x[d]
            v = fmaf(WJ[g], jn[d], v);
            if constexpr ((m & 1) && g < 4) {
                constexpr int sidx = M2I(m ^ 1);
                v = fmaf(VG[g], gp[sidx], v);
                v = fmaf(VJ[g], jn[sidx], v);
            }
            o[d] = v;
        });
        o[0] += bg[0] + bj[0];

        stage[swz(tid, 0)] = make_float4(o[0],  o[1],  o[2],  o[3]);
        stage[swz(tid, 1)] = make_float4(o[4],  o[5],  o[6],  o[7]);
        stage[swz(tid, 2)] = make_float4(o[8],  o[9],  o[10], o[11]);
        stage[swz(tid, 3)] = make_float4(o[12], o[13], o[14], o[15]);
    }
    __syncthreads();

    // ---- coalesced store from swizzled smem ----
    #pragma unroll
    for (int k = 0; k < 4; k++) {
        int f = tid + k * TPB;
        if (f < nf4) out4[f] = stage[swz(f >> 2, f & 3)];
    }
}

extern "C" void kernel_launch(void* const* d_in, const int* in_sizes, int n_in,
                              void* d_out, int out_size)
{
    const float* x  = (const float*)d_in[0];
    const float* w1 = (const float*)d_in[1];
    const float* v1 = (const float*)d_in[2];
    const float* b1 = (const float*)d_in[3];
    const float* wg = (const float*)d_in[4];
    const float* vg = (const float*)d_in[5];
    const float* bg = (const float*)d_in[6];
    const float* wj = (const float*)d_in[7];
    const float* vj = (const float*)d_in[8];
    const float* bj = (const float*)d_in[9];

    const int ntok   = in_sizes[0] / 16;
    const int blocks = (ntok + TPB - 1) / TPB;

    mvffn_kernel<<<blocks, TPB>>>(x, w1, v1, b1, wg, vg, bg, wj, vj, bj,
                                  (float*)d_out, ntok);
}